// round 3
// baseline (speedup 1.0000x reference)
#include <cuda_runtime.h>
#include <math.h>

// Problem constants (fixed by setup_inputs)
#define XY 10
#define Zdim 5
#define S 500
#define NT 10000
#define Bsz 32
#define Tlen 40
#define Llen 20
#define NEGV (-1e9f)
#define LOG2E 1.4426950408889634f
#define LN2   0.6931471805599453f

__device__ __forceinline__ float ex2(float x) {
    float r; asm("ex2.approx.ftz.f32 %0, %1;" : "=f"(r) : "f"(x)); return r;
}
__device__ __forceinline__ float lg2(float x) {
    float r; asm("lg2.approx.ftz.f32 %0, %1;" : "=f"(r) : "f"(x)); return r;
}

// ---------------------------------------------------------------------------
// Kernel 1: emission sums (transpose-free), pre-scaled to log2 domain.
// Each block owns 2 states (2 rows of logE in shared, interleaved [tok][2]).
// ---------------------------------------------------------------------------
__global__ void __launch_bounds__(512, 2) em_kernel(
    const float* __restrict__ logE,
    const int* __restrict__ stories,
    float* __restrict__ out)
{
    extern __shared__ float sh[];          // [NT][2] interleaved = 80000 B
    const int s0 = blockIdx.x * 2;

    const float4* r0 = (const float4*)(logE + (long)s0 * NT);
    const float4* r1 = (const float4*)(logE + (long)(s0 + 1) * NT);
    for (int i = threadIdx.x; i < NT / 4; i += blockDim.x) {
        float4 a = __ldg(&r0[i]);
        float4 b = __ldg(&r1[i]);
        int t4 = i * 4;
        sh[(t4 + 0) * 2 + 0] = a.x; sh[(t4 + 0) * 2 + 1] = b.x;
        sh[(t4 + 1) * 2 + 0] = a.y; sh[(t4 + 1) * 2 + 1] = b.y;
        sh[(t4 + 2) * 2 + 0] = a.z; sh[(t4 + 2) * 2 + 1] = b.z;
        sh[(t4 + 3) * 2 + 0] = a.w; sh[(t4 + 3) * 2 + 1] = b.w;
    }
    __syncthreads();

    const float2* sh2 = (const float2*)sh;
    for (int bt = threadIdx.x; bt < Bsz * Tlen; bt += blockDim.x) {
        const int4* tp = (const int4*)(stories + bt * Llen);
        int4 q0 = __ldg(&tp[0]);
        int4 q1 = __ldg(&tp[1]);
        int4 q2 = __ldg(&tp[2]);
        int4 q3 = __ldg(&tp[3]);
        int4 q4 = __ldg(&tp[4]);
        float ax = 0.f, ay = 0.f;
#define GATH(tk) { float2 v = sh2[tk]; ax += v.x; ay += v.y; }
        GATH(q0.x) GATH(q0.y) GATH(q0.z) GATH(q0.w)
        GATH(q1.x) GATH(q1.y) GATH(q1.z) GATH(q1.w)
        GATH(q2.x) GATH(q2.y) GATH(q2.z) GATH(q2.w)
        GATH(q3.x) GATH(q3.y) GATH(q3.z) GATH(q3.w)
        GATH(q4.x) GATH(q4.y) GATH(q4.z) GATH(q4.w)
#undef GATH
        int b = bt / Tlen;
        int t = bt % Tlen;
        float2* op = (float2*)(out + ((long)t * Bsz + b) * S + s0);
        *op = make_float2(ax * LOG2E, ay * LOG2E);   // log2 domain
    }
}

// ---------------------------------------------------------------------------
// Kernel 2: forward recursion in log2 domain. One block per story; alpha
// double-buffered in shared; 7-sparse stencil in registers; incremental
// pointers (no per-step 64-bit address rebuild).
// ---------------------------------------------------------------------------
__global__ void __launch_bounds__(512, 1) forward_kernel(
    const float* __restrict__ prior,
    const float* __restrict__ logT,
    float* __restrict__ out)
{
    __shared__ float buf[2][512];
    const int s = threadIdx.x;
    const int b = blockIdx.x;
    const bool act = (s < S);

    float w2[7];
    int   nb[7];
    if (act) {
        int z = s / (XY * XY);
        int r = s % (XY * XY);
        int y = r / XY;
        int x = r % XY;
        const float* row = logT + (long)s * S;
        bool v1 = (x + 1 < XY), v2 = (x - 1 >= 0);
        bool v3 = (y + 1 < XY), v4 = (y - 1 >= 0);
        bool v5 = (z + 1 < Zdim), v6 = (z + 2 < Zdim);
        nb[0] = s;                     w2[0] = __ldg(&row[s]) * LOG2E;
        nb[1] = v1 ? s + 1   : s;      w2[1] = v1 ? __ldg(&row[s + 1]) * LOG2E   : NEGV;
        nb[2] = v2 ? s - 1   : s;      w2[2] = v2 ? __ldg(&row[s - 1]) * LOG2E   : NEGV;
        nb[3] = v3 ? s + XY  : s;      w2[3] = v3 ? __ldg(&row[s + XY]) * LOG2E  : NEGV;
        nb[4] = v4 ? s - XY  : s;      w2[4] = v4 ? __ldg(&row[s - XY]) * LOG2E  : NEGV;
        nb[5] = v5 ? s + XY*XY   : s;  w2[5] = v5 ? __ldg(&row[s + XY*XY]) * LOG2E   : NEGV;
        nb[6] = v6 ? s + 2*XY*XY : s;  w2[6] = v6 ? __ldg(&row[s + 2*XY*XY]) * LOG2E : NEGV;
    }

    // t = 0: alpha0 = em0 + prior (both log2 domain; em already in out)
    if (act) {
        float a0 = out[b * S + s] + __ldg(&prior[s]) * LOG2E;
        out[b * S + s] = a0 * LN2;      // output in natural log
        buf[0][s] = a0;
    }
    __syncthreads();

    // incremental pointers for this (b, s) lane, starting at t=1
    const float* ep = out + (Bsz + b) * S + s;   // em2 read location
    float*       op = out + (Bsz + b) * S + s;   // alpha write location

    float em_next = act ? *ep : 0.0f;
    ep += Bsz * S;

    int cur = 0;
#pragma unroll 1
    for (int t = 1; t < Tlen; t++) {
        float em_t = em_next;
        if (act && t + 1 < Tlen) em_next = *ep;
        ep += Bsz * S;

        if (act) {
            float v0 = w2[0] + buf[cur][nb[0]];
            float v1 = w2[1] + buf[cur][nb[1]];
            float v2 = w2[2] + buf[cur][nb[2]];
            float v3 = w2[3] + buf[cur][nb[3]];
            float v4 = w2[4] + buf[cur][nb[4]];
            float v5 = w2[5] + buf[cur][nb[5]];
            float v6 = w2[6] + buf[cur][nb[6]];
            // max tree
            float m01 = fmaxf(v0, v1), m23 = fmaxf(v2, v3);
            float m45 = fmaxf(v4, v5);
            float m = fmaxf(fmaxf(m01, m23), fmaxf(m45, v6));
            float sum = ex2(v0 - m) + ex2(v1 - m) + ex2(v2 - m) + ex2(v3 - m)
                      + ex2(v4 - m) + ex2(v5 - m) + ex2(v6 - m);
            float a = em_t + m + lg2(sum);
            buf[cur ^ 1][s] = a;
            *op = a * LN2;
        }
        op += Bsz * S;
        __syncthreads();
        cur ^= 1;
    }
}

// ---------------------------------------------------------------------------
extern "C" void kernel_launch(void* const* d_in, const int* in_sizes, int n_in,
                              void* d_out, int out_size) {
    const float* log_priors      = (const float*)d_in[0];
    const float* log_transitions = (const float*)d_in[1];
    const float* log_emissions   = (const float*)d_in[2];
    const int*   stories         = (const int*)d_in[3];
    float* out = (float*)d_out;

    static bool attr_set = false;
    if (!attr_set) {
        cudaFuncSetAttribute(em_kernel,
                             cudaFuncAttributeMaxDynamicSharedMemorySize,
                             NT * 2 * (int)sizeof(float));
        attr_set = true;
    }

    em_kernel<<<S / 2, 512, NT * 2 * sizeof(float)>>>(log_emissions, stories, out);
    forward_kernel<<<Bsz, 512>>>(log_priors, log_transitions, out);
}

// round 10
// speedup vs baseline: 1.0692x; 1.0692x over previous
#include <cuda_runtime.h>
#include <math.h>

// Problem constants (fixed by setup_inputs)
#define XY 10
#define Zdim 5
#define S 500
#define NT 10000
#define Bsz 32
#define Tlen 40
#define Llen 20
#define LOG2E 1.4426950408889634f
#define LN2   0.6931471805599453f

__device__ __forceinline__ float ex2(float x) {
    float r; asm("ex2.approx.ftz.f32 %0, %1;" : "=f"(r) : "f"(x)); return r;
}
__device__ __forceinline__ float lg2(float x) {
    float r; asm("lg2.approx.ftz.f32 %0, %1;" : "=f"(r) : "f"(x)); return r;
}

// ---------------------------------------------------------------------------
// Kernel 1: emission sums (transpose-free), output in log2 domain.
// Each block owns 2 states (2 rows of logE in shared, interleaved [tok][2]).
// ---------------------------------------------------------------------------
__global__ void __launch_bounds__(512, 2) em_kernel(
    const float* __restrict__ logE,
    const int* __restrict__ stories,
    float* __restrict__ out)
{
    extern __shared__ float sh[];          // [NT][2] interleaved = 80000 B
    const int s0 = blockIdx.x * 2;

    const float4* r0 = (const float4*)(logE + (long)s0 * NT);
    const float4* r1 = (const float4*)(logE + (long)(s0 + 1) * NT);
    for (int i = threadIdx.x; i < NT / 4; i += blockDim.x) {
        float4 a = __ldg(&r0[i]);
        float4 b = __ldg(&r1[i]);
        int t4 = i * 4;
        sh[(t4 + 0) * 2 + 0] = a.x; sh[(t4 + 0) * 2 + 1] = b.x;
        sh[(t4 + 1) * 2 + 0] = a.y; sh[(t4 + 1) * 2 + 1] = b.y;
        sh[(t4 + 2) * 2 + 0] = a.z; sh[(t4 + 2) * 2 + 1] = b.z;
        sh[(t4 + 3) * 2 + 0] = a.w; sh[(t4 + 3) * 2 + 1] = b.w;
    }
    __syncthreads();

    const float2* sh2 = (const float2*)sh;
    for (int bt = threadIdx.x; bt < Bsz * Tlen; bt += blockDim.x) {
        const int4* tp = (const int4*)(stories + bt * Llen);
        int4 q0 = __ldg(&tp[0]);
        int4 q1 = __ldg(&tp[1]);
        int4 q2 = __ldg(&tp[2]);
        int4 q3 = __ldg(&tp[3]);
        int4 q4 = __ldg(&tp[4]);
        float ax = 0.f, ay = 0.f;
#define GATH(tk) { float2 v = sh2[tk]; ax += v.x; ay += v.y; }
        GATH(q0.x) GATH(q0.y) GATH(q0.z) GATH(q0.w)
        GATH(q1.x) GATH(q1.y) GATH(q1.z) GATH(q1.w)
        GATH(q2.x) GATH(q2.y) GATH(q2.z) GATH(q2.w)
        GATH(q3.x) GATH(q3.y) GATH(q3.z) GATH(q3.w)
        GATH(q4.x) GATH(q4.y) GATH(q4.z) GATH(q4.w)
#undef GATH
        int b = bt / Tlen;
        int t = bt % Tlen;
        float2* op = (float2*)(out + ((long)t * Bsz + b) * S + s0);
        *op = make_float2(ax * LOG2E, ay * LOG2E);   // log2 domain
    }
}

// ---------------------------------------------------------------------------
// Kernel 2: forward recursion, linear mantissa + per-state int32 exponent.
// p[s] = m[s] * 2^e[s], m in [1,2). Recurrence path is pure FFMA/ALU;
// the 2 MUFU ops (ex2 on prefetched em, lg2 for output) are off-path.
// ---------------------------------------------------------------------------
__global__ void __launch_bounds__(512, 1) forward_kernel(
    const float* __restrict__ prior,
    const float* __restrict__ logT,
    float* __restrict__ out)
{
    __shared__ float2 buf[2][512];   // {mantissa, exponent-as-float-bits}
    const int s = threadIdx.x;
    const int b = blockIdx.x;
    const bool act = (s < S);
    const int BS = Bsz * S;

    // Linear-domain sparse transition row (7-neighbor stencil)
    float w[7];
    int   nb[7];
    if (act) {
        int z = s / (XY * XY);
        int r = s % (XY * XY);
        int y = r / XY;
        int x = r % XY;
        const float* row = logT + (long)s * S;
        bool v1 = (x + 1 < XY), v2 = (x - 1 >= 0);
        bool v3 = (y + 1 < XY), v4 = (y - 1 >= 0);
        bool v5 = (z + 1 < Zdim), v6 = (z + 2 < Zdim);
        nb[0] = s;                     w[0] = ex2(__ldg(&row[s]) * LOG2E);
        nb[1] = v1 ? s + 1   : s;      w[1] = v1 ? ex2(__ldg(&row[s + 1]) * LOG2E)   : 0.f;
        nb[2] = v2 ? s - 1   : s;      w[2] = v2 ? ex2(__ldg(&row[s - 1]) * LOG2E)   : 0.f;
        nb[3] = v3 ? s + XY  : s;      w[3] = v3 ? ex2(__ldg(&row[s + XY]) * LOG2E)  : 0.f;
        nb[4] = v4 ? s - XY  : s;      w[4] = v4 ? ex2(__ldg(&row[s - XY]) * LOG2E)  : 0.f;
        nb[5] = v5 ? s + XY*XY   : s;  w[5] = v5 ? ex2(__ldg(&row[s + XY*XY]) * LOG2E)   : 0.f;
        nb[6] = v6 ? s + 2*XY*XY : s;  w[6] = v6 ? ex2(__ldg(&row[s + 2*XY*XY]) * LOG2E) : 0.f;
    }

    // t = 0: alpha2_0 = em2_0 + prior2 (log2 domain). Split into (m, e).
    if (act) {
        float a2 = out[b * S + s] + __ldg(&prior[s]) * LOG2E;
        out[b * S + s] = a2 * LN2;                // natural-log output
        int   e0 = __float2int_rd(a2);
        float m0 = ex2(a2 - (float)e0);           // in [1,2)
        buf[0][s] = make_float2(m0, __int_as_float(e0));
    }

    // Prefetch em for t=1, t=2
    const float* ep = out + (Bsz + b) * S + s;
    float emA = act ? __ldg(&ep[0])  : 0.f;
    float emB = act ? __ldg(&ep[BS]) : 0.f;
    ep += 2 * BS;
    __syncthreads();

    float* op = out + (Bsz + b) * S + s;
    int cur = 0;
#pragma unroll 1
    for (int t = 1; t < Tlen; t++) {
        float em_t = emA;
        emA = emB;
        if (act && t + 2 < Tlen) emB = __ldg(ep);
        ep += BS;

        if (act) {
            // em preprocessing (off the recurrence critical path)
            int   fi  = __float2int_rd(em_t);
            float fr  = em_t - (float)fi;
            float exf = ex2(fr);                  // in [1,2), 1 MUFU

            // Load 7 neighbors (m, e)
            const float2* pb = buf[cur];
            float2 n0 = pb[nb[0]], n1 = pb[nb[1]], n2 = pb[nb[2]], n3 = pb[nb[3]];
            float2 n4 = pb[nb[4]], n5 = pb[nb[5]], n6 = pb[nb[6]];
            int e0 = __float_as_int(n0.y), e1 = __float_as_int(n1.y);
            int e2 = __float_as_int(n2.y), e3 = __float_as_int(n3.y);
            int e4 = __float_as_int(n4.y), e5 = __float_as_int(n5.y);
            int e6 = __float_as_int(n6.y);

            int emax = max(max(max(e0, e1), max(e2, e3)),
                           max(max(e4, e5), e6));

            // scale_k = 2^(e_k - emax) via exact exponent-bit construction
#define SCL(ek) __int_as_float(max((ek) - emax + 127, 0) << 23)
            float q = w[0] * n0.x * SCL(e0);
            q = fmaf(w[1] * n1.x, SCL(e1), q);
            q = fmaf(w[2] * n2.x, SCL(e2), q);
            q = fmaf(w[3] * n3.x, SCL(e3), q);
            q = fmaf(w[4] * n4.x, SCL(e4), q);
            q = fmaf(w[5] * n5.x, SCL(e5), q);
            q = fmaf(w[6] * n6.x, SCL(e6), q);
#undef SCL
            // q in [~2^-13, 2^9] always (argmax-exponent term has scale 1)

            // Renormalize: q = mq * 2^eq, mq in [1,2)
            int   qb = __float_as_int(q);
            int   eq = (qb >> 23) - 127;
            float mq = __int_as_float((qb & 0x007FFFFF) | 0x3F800000);

            // Fold emission: m2 = mq * exf in [1,4); renormalize again
            float m2v = mq * exf;
            int   b2  = __float_as_int(m2v);
            int   ea  = (b2 >> 23) - 127;         // 0 or 1
            float mf  = __int_as_float((b2 & 0x007FFFFF) | 0x3F800000);
            int   ef  = emax + eq + fi + ea;      // exact int arithmetic

            buf[cur ^ 1][s] = make_float2(mf, __int_as_float(ef));

            // Output alpha (natural log); lg2 only feeds the store
            float a2 = (float)ef + lg2(mf);
            *op = a2 * LN2;
        }
        op += BS;
        __syncthreads();
        cur ^= 1;
    }
}

// ---------------------------------------------------------------------------
extern "C" void kernel_launch(void* const* d_in, const int* in_sizes, int n_in,
                              void* d_out, int out_size) {
    const float* log_priors      = (const float*)d_in[0];
    const float* log_transitions = (const float*)d_in[1];
    const float* log_emissions   = (const float*)d_in[2];
    const int*   stories         = (const int*)d_in[3];
    float* out = (float*)d_out;

    static bool attr_set = false;
    if (!attr_set) {
        cudaFuncSetAttribute(em_kernel,
                             cudaFuncAttributeMaxDynamicSharedMemorySize,
                             NT * 2 * (int)sizeof(float));
        attr_set = true;
    }

    em_kernel<<<S / 2, 512, NT * 2 * sizeof(float)>>>(log_emissions, stories, out);
    forward_kernel<<<Bsz, 512>>>(log_priors, log_transitions, out);
}